// round 3
// baseline (speedup 1.0000x reference)
#include <cuda_runtime.h>
#include <math.h>

// =====================================================================
// FrFTPool: out = |A · X · B^T| per 128x128 image; A,B (64x128 complex)
// built on-device from the Candan/Ozaktas FrFT closed form with the
// center crop folded in. GEMMs use packed fma.rn.f32x2 (FFMA2).
// =====================================================================

#define NBIG 128
#define NSMALL 64
#define NIMG 256          // 8*32
#define XS_ROW 132        // padded row for transposed X in smem (floats)
#define TS_ROW 66         // padded row for T in smem (float2)
#define KCHUNK 32         // k/p tile depth for Tile staging

typedef unsigned long long u64v;

__device__ __forceinline__ u64v pk2(float lo, float hi) {
    u64v r; asm("mov.b64 %0, {%1, %2};" : "=l"(r) : "f"(lo), "f"(hi)); return r;
}
__device__ __forceinline__ void upk2(float& lo, float& hi, u64v v) {
    asm("mov.b64 {%0, %1}, %2;" : "=f"(lo), "=f"(hi) : "l"(v));
}
__device__ __forceinline__ void ffma2(u64v& d, u64v a, u64v b) {
    asm("fma.rn.f32x2 %0, %1, %2, %0;" : "+l"(d) : "l"(a), "l"(b));
}

// ---------------- device scratch (no allocations allowed) -------------
__device__ __align__(16) float2 d_M1[NBIG * NBIG];
__device__ __align__(16) float2 d_M2[NBIG * NBIG];
__device__ __align__(16) float2 d_M3[NSMALL * NSMALL];
__device__ __align__(16) float2 d_M4[NSMALL * NSMALL];
__device__ __align__(16) float2 d_At[NBIG * NSMALL];   // At[h][i] = A[i][h]
__device__ __align__(16) float2 d_Bt[NBIG * NSMALL];   // Bt[k][j] = B[j][k]

// ---------------- 1) FrFT matrices, fused tables ----------------------
// matrix m: 0 -> order1 @N=128, 1 -> order2 @N=128,
//           2 -> -order1 @N=64,  3 -> -order2 @N=64
// M[j,k] = pref*C[2j]*( K[2(j-kk)]*C[2kk] + sum_t KC[t]*w[idx(t,kk)] )
//   kk = flip ? N-1-k : k,  KC[t] = K[2j-2t-1]*C[2t+1],
//   w[i] = ((i&1)?-2:2)/(pi*(2i+1)),  idx = u^(u>>31), u = t-kk
__global__ void build_matrix_fused(const float* __restrict__ order1,
                                   const float* __restrict__ order2) {
    int m = blockIdx.y;
    int N = (m < 2) ? NBIG : NSMALL;
    int j = blockIdx.x;
    if (j >= N) return;

    float ap = ((m == 0) || (m == 2)) ? order1[0] : order2[0];
    if (m >= 2) ap = -ap;
    double a = fmod((double)ap, 4.0);
    if (a < 0.0) a += 4.0;
    int flip = 0;
    if (a > 2.0) { flip = 1; a -= 2.0; }
    double alpha = a * M_PI * 0.5;
    double tana2 = tan(alpha * 0.5);
    double sina  = sin(alpha);
    double c     = M_PI / (4.0 * (double)N * sina);
    double kch   = (M_PI / (double)N) * tana2 * 0.25;

    __shared__ float2 Ks[4 * NBIG];    // 4N-3 <= 509
    __shared__ float2 Cs[2 * NBIG];    // 2N-1 <= 255
    __shared__ float  W[NBIG];         // sinc weights
    __shared__ float2 KC[NBIG];        // hoisted K*C per t

    int tid = threadIdx.x;
    for (int i = tid; i < 4 * N - 3; i += 128) {
        double mm = (double)(i - (2 * N - 2));
        double s, co; sincos(c * mm * mm, &s, &co);
        Ks[i] = make_float2((float)co, (float)s);
    }
    for (int p = tid; p < 2 * N - 1; p += 128) {
        double n = (double)(p - (N - 1));
        double s, co; sincos(-kch * n * n, &s, &co);
        Cs[p] = make_float2((float)co, (float)s);
    }
    if (tid < N)
        W[tid] = ((tid & 1) ? -2.0f : 2.0f) / ((float)M_PI * (float)(2 * tid + 1));
    __syncthreads();

    int off = 2 * N - 2;
    if (tid < N - 1) {
        float2 K = Ks[2 * j - 2 * tid - 1 + off];
        float2 C = Cs[2 * tid + 1];
        KC[tid] = make_float2(K.x * C.x - K.y * C.y, K.x * C.y + K.y * C.x);
    }
    __syncthreads();

    int k = tid;
    if (k >= N) return;
    int kk = flip ? (N - 1 - k) : k;

    float2 Ke = Ks[2 * (j - kk) + off];
    float2 Ce = Cs[2 * kk];
    float sr = Ke.x * Ce.x - Ke.y * Ce.y;
    float si = Ke.x * Ce.y + Ke.y * Ce.x;

    for (int t = 0; t < N - 1; t++) {
        int u = t - kk;
        int idx = u ^ (u >> 31);
        float sv = W[idx];
        float2 kc = KC[t];
        sr = fmaf(kc.x, sv, sr);
        si = fmaf(kc.y, sv, si);
    }

    double ph = -(1.0 - a) * M_PI * 0.25;
    double s, co; sincos(ph, &s, &co);
    double sc = sqrt(c / M_PI);
    float prx = (float)(co * sc), pry = (float)(s * sc);
    float2 Cj = Cs[2 * j];
    float pcr = prx * Cj.x - pry * Cj.y;
    float pci = prx * Cj.y + pry * Cj.x;
    float2 outv;
    outv.x = pcr * sr - pci * si;
    outv.y = pcr * si + pci * sr;

    float2* M = (m == 0) ? d_M1 : (m == 1) ? d_M2 : (m == 2) ? d_M3 : d_M4;
    M[j * N + k] = outv;
}

// ---------------- 2) fold crop into combined matrices -----------------
// A[i,h] = sum_p M4[i,p] * M2[32+p, h]   -> stored transposed At[h][i]
// B[j,k] = sum_q M3[j,q] * M1[32+q, k]   -> stored transposed Bt[k][j]
__global__ void combine() {
    int i = blockIdx.x;          // 0..63 output row of A/B
    int h = threadIdx.x;         // 0..127 input column
    const float2* L = blockIdx.y ? d_M3 : d_M4;   // 64x64
    const float2* R = blockIdx.y ? d_M1 : d_M2;   // 128x128
    float ar = 0.f, ai = 0.f;
    for (int p = 0; p < NSMALL; p++) {
        float2 l = L[i * NSMALL + p];
        float2 r = R[(32 + p) * NBIG + h];
        ar += l.x * r.x - l.y * r.y;
        ai += l.x * r.y + l.y * r.x;
    }
    float2* T = blockIdx.y ? d_Bt : d_At;
    T[h * NSMALL + i] = make_float2(ar, ai);
}

// ---------------- 3) main fused kernel: per-image |A·X·B^T| -----------
// block = 256 threads, one image per block.
// GEMM1: T[p,j] = sum_k X[p,k]*B[j,k]   (X real)   p<128, j<64
// GEMM2: O[i,j] = | sum_p A[i,p]*T[p,j] |          i<64,  j<64
#define SMEM_BYTES (NBIG * XS_ROW * 4 + KCHUNK * NSMALL * 8)  // 67584 + 16384

__global__ __launch_bounds__(256, 2)
void frft_pool_main(const float* __restrict__ x, float* __restrict__ out) {
    extern __shared__ float smem[];
    float*  Xs   = smem;                                // [128][132] floats
    float2* Tile = (float2*)(smem + NBIG * XS_ROW);     // [KCHUNK][64] float2

    int tid = threadIdx.x;
    int l = tid & 31;        // lane
    int w = tid >> 5;        // warp 0..7
    int img = blockIdx.x;

    // --- load X transposed into smem: Xs[k][p] = X[p][k] ---
    const float4* xg4 = (const float4*)(x + (size_t)img * (NBIG * NBIG));
    #pragma unroll
    for (int i = 0; i < 16; i++) {
        int idx4 = tid + i * 256;
        float4 v = xg4[idx4];
        int r = idx4 >> 5;            // row p
        int c = (idx4 & 31) << 2;     // col k base
        Xs[(c + 0) * XS_ROW + r] = v.x;
        Xs[(c + 1) * XS_ROW + r] = v.y;
        Xs[(c + 2) * XS_ROW + r] = v.z;
        Xs[(c + 3) * XS_ROW + r] = v.w;
    }

    // ---- GEMM1: thread computes T[4l..4l+3][8w..8w+7], packed (re,im) ----
    u64v acc[4][8];
    #pragma unroll
    for (int pp = 0; pp < 4; pp++)
        #pragma unroll
        for (int jj = 0; jj < 8; jj++) acc[pp][jj] = 0ull;

    for (int k0 = 0; k0 < NBIG; k0 += KCHUNK) {
        __syncthreads();
        {
            const ulonglong2* g = (const ulonglong2*)(d_Bt + (size_t)k0 * NSMALL);
            ulonglong2* t = (ulonglong2*)Tile;
            #pragma unroll
            for (int i = 0; i < (KCHUNK * NSMALL) / (2 * 256); i++)
                t[tid + i * 256] = g[tid + i * 256];
        }
        __syncthreads();
        #pragma unroll
        for (int kt = 0; kt < KCHUNK; kt++) {
            int k = k0 + kt;
            float4 xv = *(const float4*)&Xs[k * XS_ROW + 4 * l];
            const ulonglong2* bp = (const ulonglong2*)&Tile[kt * NSMALL + 8 * w];
            ulonglong2 b0 = bp[0], b1 = bp[1], b2 = bp[2], b3 = bp[3];
            u64v bb[8] = {b0.x, b0.y, b1.x, b1.y, b2.x, b2.y, b3.x, b3.y};
            float xsv[4] = {xv.x, xv.y, xv.z, xv.w};
            #pragma unroll
            for (int pp = 0; pp < 4; pp++) {
                u64v xs2 = pk2(xsv[pp], xsv[pp]);
                #pragma unroll
                for (int jj = 0; jj < 8; jj++) ffma2(acc[pp][jj], xs2, bb[jj]);
            }
        }
    }

    // --- write T into smem (reusing Xs region): Ts[p][j], row pitch 66 ---
    __syncthreads();
    float2* Ts = (float2*)smem;
    #pragma unroll
    for (int pp = 0; pp < 4; pp++)
        #pragma unroll
        for (int jp = 0; jp < 4; jp++)
            *(ulonglong2*)&Ts[(4 * l + pp) * TS_ROW + 8 * w + 2 * jp] =
                make_ulonglong2(acc[pp][2 * jp], acc[pp][2 * jp + 1]);

    // ---- GEMM2: thread computes O[{l,l+32}][8w..8w+7] ----
    // accA = sum a.re*(t.re,t.im), accB = sum a.im*(t.re,t.im)
    u64v accA[2][8], accB[2][8];
    #pragma unroll
    for (int ii = 0; ii < 2; ii++)
        #pragma unroll
        for (int jj = 0; jj < 8; jj++) { accA[ii][jj] = 0ull; accB[ii][jj] = 0ull; }

    for (int p0 = 0; p0 < NBIG; p0 += KCHUNK) {
        __syncthreads();
        {
            const ulonglong2* g = (const ulonglong2*)(d_At + (size_t)p0 * NSMALL);
            ulonglong2* t = (ulonglong2*)Tile;
            #pragma unroll
            for (int i = 0; i < (KCHUNK * NSMALL) / (2 * 256); i++)
                t[tid + i * 256] = g[tid + i * 256];
        }
        __syncthreads();
        #pragma unroll
        for (int pt = 0; pt < KCHUNK; pt++) {
            int p = p0 + pt;
            float2 a0 = Tile[pt * NSMALL + l];
            float2 a1 = Tile[pt * NSMALL + l + 32];
            const ulonglong2* tp = (const ulonglong2*)&Ts[p * TS_ROW + 8 * w];
            ulonglong2 t0 = tp[0], t1 = tp[1], t2 = tp[2], t3 = tp[3];
            u64v tt[8] = {t0.x, t0.y, t1.x, t1.y, t2.x, t2.y, t3.x, t3.y};
            u64v ax0 = pk2(a0.x, a0.x), ay0 = pk2(a0.y, a0.y);
            u64v ax1 = pk2(a1.x, a1.x), ay1 = pk2(a1.y, a1.y);
            #pragma unroll
            for (int jj = 0; jj < 8; jj++) {
                ffma2(accA[0][jj], ax0, tt[jj]);
                ffma2(accB[0][jj], ay0, tt[jj]);
                ffma2(accA[1][jj], ax1, tt[jj]);
                ffma2(accB[1][jj], ay1, tt[jj]);
            }
        }
    }

    float* og = out + (size_t)img * (NSMALL * NSMALL);
    #pragma unroll
    for (int ii = 0; ii < 2; ii++) {
        int i = l + 32 * ii;
        float res[8];
        #pragma unroll
        for (int jj = 0; jj < 8; jj++) {
            float Ar, Ai, Br, Bi;
            upk2(Ar, Ai, accA[ii][jj]);
            upk2(Br, Bi, accB[ii][jj]);
            float orr = Ar - Bi;
            float oii = Ai + Br;
            res[jj] = sqrtf(orr * orr + oii * oii);
        }
        *(float4*)&og[i * NSMALL + 8 * w]     = make_float4(res[0], res[1], res[2], res[3]);
        *(float4*)&og[i * NSMALL + 8 * w + 4] = make_float4(res[4], res[5], res[6], res[7]);
    }
}

// ---------------------------------------------------------------------
extern "C" void kernel_launch(void* const* d_in, const int* in_sizes, int n_in,
                              void* d_out, int out_size) {
    const float* x  = (const float*)d_in[0];
    const float* o1 = (const float*)d_in[1];
    const float* o2 = (const float*)d_in[2];
    float* out = (float*)d_out;

    build_matrix_fused<<<dim3(NBIG, 4), 128>>>(o1, o2);
    combine<<<dim3(NSMALL, 2), 128>>>();

    cudaFuncSetAttribute(frft_pool_main,
                         cudaFuncAttributeMaxDynamicSharedMemorySize, SMEM_BYTES);
    frft_pool_main<<<NIMG, 256, SMEM_BYTES>>>(x, out);
}

// round 4
// speedup vs baseline: 1.2117x; 1.2117x over previous
#include <cuda_runtime.h>
#include <math.h>

// =====================================================================
// FrFTPool: out = |A · X · B^T| per 128x128 image; A,B (64x128 complex)
// built on-device from the Candan/Ozaktas FrFT closed form with the
// center crop folded in. GEMMs use packed fma.rn.f32x2 (FFMA2).
// =====================================================================

#define NBIG 128
#define NSMALL 64
#define NIMG 256          // 8*32
#define XS_ROW 132        // padded row for transposed X in smem (floats)
#define TS_ROW 66         // padded row for T in smem (float2)
#define KCHUNK 32         // k/p tile depth for Tile staging

typedef unsigned long long u64v;

__device__ __forceinline__ u64v pk2(float lo, float hi) {
    u64v r; asm("mov.b64 %0, {%1, %2};" : "=l"(r) : "f"(lo), "f"(hi)); return r;
}
__device__ __forceinline__ void upk2(float& lo, float& hi, u64v v) {
    asm("mov.b64 {%0, %1}, %2;" : "=f"(lo), "=f"(hi) : "l"(v));
}
__device__ __forceinline__ void ffma2(u64v& d, u64v a, u64v b) {
    asm("fma.rn.f32x2 %0, %1, %2, %0;" : "+l"(d) : "l"(a), "l"(b));
}

// ---------------- device scratch (no allocations allowed) -------------
__device__ __align__(16) float2 d_M1[NBIG * NBIG];
__device__ __align__(16) float2 d_M2[NBIG * NBIG];
__device__ __align__(16) float2 d_M3[NSMALL * NSMALL];
__device__ __align__(16) float2 d_M4[NSMALL * NSMALL];
__device__ __align__(16) float2 d_At[NBIG * NSMALL];   // At[h][i] = A[i][h]
__device__ __align__(16) float2 d_Bt[NBIG * NSMALL];   // Bt[k][j] = B[j][k]

__device__ __align__(16) float2 d_Ktab[4][4 * NBIG];   // up to 4N-3 = 509
__device__ __align__(16) float2 d_Ctab[4][2 * NBIG];   // up to 2N-1 = 255
__device__ float2 d_pref[4];
__device__ int    d_flip[4];

// ---------------- 1) chirp tables, ONCE per matrix (DP sincos) --------
// matrix m: 0 -> order1 @N=128, 1 -> order2 @N=128,
//           2 -> -order1 @N=64,  3 -> -order2 @N=64
__global__ void build_tables(const float* __restrict__ order1,
                             const float* __restrict__ order2) {
    int m = blockIdx.x;
    int N = (m < 2) ? NBIG : NSMALL;
    float ap = ((m == 0) || (m == 2)) ? order1[0] : order2[0];
    if (m >= 2) ap = -ap;

    double a = fmod((double)ap, 4.0);
    if (a < 0.0) a += 4.0;
    int flip = 0;
    if (a > 2.0) { flip = 1; a -= 2.0; }

    double alpha = a * M_PI * 0.5;
    double tana2 = tan(alpha * 0.5);
    double sina  = sin(alpha);
    double c     = M_PI / (4.0 * (double)N * sina);
    double kch   = (M_PI / (double)N) * tana2 * 0.25;

    int t = threadIdx.x;
    for (int i = t; i < 4 * N - 3; i += blockDim.x) {
        double mm = (double)(i - (2 * N - 2));
        double s, co; sincos(c * mm * mm, &s, &co);
        d_Ktab[m][i] = make_float2((float)co, (float)s);
    }
    for (int p = t; p < 2 * N - 1; p += blockDim.x) {
        double n = (double)(p - (N - 1));
        double s, co; sincos(-kch * n * n, &s, &co);
        d_Ctab[m][p] = make_float2((float)co, (float)s);
    }
    if (t == 0) {
        double ph = -(1.0 - a) * M_PI * 0.25;
        double s, co; sincos(ph, &s, &co);
        double sc = sqrt(c / M_PI);
        d_pref[m] = make_float2((float)(co * sc), (float)(s * sc));
        d_flip[m] = flip;
    }
}

// ---------------- 2) FrFT matrices from tables (fp32 only) ------------
// M[j,k] = pref*C[2j]*( K[2(j-kk)]*C[2kk] + sum_t KC[t]*W[|t-kk|] )
//   kk = flip ? N-1-k : k,  KC[t] = K[2j-2t-1]*C[2t+1],
//   W[i] = ((i&1)?-2:2)/(pi*(2i+1))
__global__ void build_matrix() {
    int m = blockIdx.y;
    int N = (m < 2) ? NBIG : NSMALL;
    int j = blockIdx.x;
    if (j >= N) return;

    __shared__ float2 Ks[4 * NBIG];
    __shared__ float2 Cs[2 * NBIG];
    __shared__ float  W[NBIG];
    __shared__ float2 KC[NBIG];

    int tid = threadIdx.x;
    for (int i = tid; i < 4 * N - 3; i += 128) Ks[i] = d_Ktab[m][i];
    for (int p = tid; p < 2 * N - 1; p += 128) Cs[p] = d_Ctab[m][p];
    if (tid < N)
        W[tid] = ((tid & 1) ? -2.0f : 2.0f) / ((float)M_PI * (float)(2 * tid + 1));
    __syncthreads();

    int off = 2 * N - 2;
    if (tid < N - 1) {
        float2 K = Ks[2 * j - 2 * tid - 1 + off];
        float2 C = Cs[2 * tid + 1];
        KC[tid] = make_float2(K.x * C.x - K.y * C.y, K.x * C.y + K.y * C.x);
    }
    __syncthreads();

    int k = tid;
    if (k >= N) return;
    int flip = d_flip[m];
    int kk = flip ? (N - 1 - k) : k;

    float2 Ke = Ks[2 * (j - kk) + off];
    float2 Ce = Cs[2 * kk];
    float sr = Ke.x * Ce.x - Ke.y * Ce.y;
    float si = Ke.x * Ce.y + Ke.y * Ce.x;

    #pragma unroll 4
    for (int t = 0; t < N - 1; t++) {
        int u = t - kk;
        int idx = u ^ (u >> 31);
        float sv = W[idx];
        float2 kc = KC[t];
        sr = fmaf(kc.x, sv, sr);
        si = fmaf(kc.y, sv, si);
    }

    float2 pr = d_pref[m];
    float2 Cj = Cs[2 * j];
    float pcr = pr.x * Cj.x - pr.y * Cj.y;
    float pci = pr.x * Cj.y + pr.y * Cj.x;
    float2 outv;
    outv.x = pcr * sr - pci * si;
    outv.y = pcr * si + pci * sr;

    float2* M = (m == 0) ? d_M1 : (m == 1) ? d_M2 : (m == 2) ? d_M3 : d_M4;
    M[j * N + k] = outv;
}

// ---------------- 3) fold crop into combined matrices -----------------
// A[i,h] = sum_p M4[i,p] * M2[32+p, h]   -> stored transposed At[h][i]
// B[j,k] = sum_q M3[j,q] * M1[32+q, k]   -> stored transposed Bt[k][j]
__global__ void combine() {
    int i = blockIdx.x;          // 0..63 output row of A/B
    int h = threadIdx.x;         // 0..127 input column
    const float2* L = blockIdx.y ? d_M3 : d_M4;   // 64x64
    const float2* R = blockIdx.y ? d_M1 : d_M2;   // 128x128
    float ar = 0.f, ai = 0.f;
    for (int p = 0; p < NSMALL; p++) {
        float2 l = L[i * NSMALL + p];
        float2 r = R[(32 + p) * NBIG + h];
        ar += l.x * r.x - l.y * r.y;
        ai += l.x * r.y + l.y * r.x;
    }
    float2* T = blockIdx.y ? d_Bt : d_At;
    T[h * NSMALL + i] = make_float2(ar, ai);
}

// ---------------- 4) main fused kernel: per-image |A·X·B^T| -----------
// block = 256 threads, one image per block.
// GEMM1: T[p,j] = sum_k X[p,k]*B[j,k]   (X real)   p<128, j<64
// GEMM2: O[i,j] = | sum_p A[i,p]*T[p,j] |          i<64,  j<64
#define SMEM_BYTES (NBIG * XS_ROW * 4 + KCHUNK * NSMALL * 8)  // 67584 + 16384

__global__ __launch_bounds__(256, 2)
void frft_pool_main(const float* __restrict__ x, float* __restrict__ out) {
    extern __shared__ float smem[];
    float*  Xs   = smem;                                // [128][132] floats
    float2* Tile = (float2*)(smem + NBIG * XS_ROW);     // [KCHUNK][64] float2

    int tid = threadIdx.x;
    int l = tid & 31;        // lane
    int w = tid >> 5;        // warp 0..7
    int img = blockIdx.x;

    // --- load X transposed into smem: Xs[k][p] = X[p][k] ---
    const float4* xg4 = (const float4*)(x + (size_t)img * (NBIG * NBIG));
    #pragma unroll
    for (int i = 0; i < 16; i++) {
        int idx4 = tid + i * 256;
        float4 v = xg4[idx4];
        int r = idx4 >> 5;            // row p
        int c = (idx4 & 31) << 2;     // col k base
        Xs[(c + 0) * XS_ROW + r] = v.x;
        Xs[(c + 1) * XS_ROW + r] = v.y;
        Xs[(c + 2) * XS_ROW + r] = v.z;
        Xs[(c + 3) * XS_ROW + r] = v.w;
    }

    // ---- GEMM1: thread computes T[4l..4l+3][8w..8w+7], packed (re,im) ----
    u64v acc[4][8];
    #pragma unroll
    for (int pp = 0; pp < 4; pp++)
        #pragma unroll
        for (int jj = 0; jj < 8; jj++) acc[pp][jj] = 0ull;

    for (int k0 = 0; k0 < NBIG; k0 += KCHUNK) {
        __syncthreads();
        {
            const ulonglong2* g = (const ulonglong2*)(d_Bt + (size_t)k0 * NSMALL);
            ulonglong2* t = (ulonglong2*)Tile;
            #pragma unroll
            for (int i = 0; i < (KCHUNK * NSMALL) / (2 * 256); i++)
                t[tid + i * 256] = g[tid + i * 256];
        }
        __syncthreads();
        #pragma unroll
        for (int kt = 0; kt < KCHUNK; kt++) {
            int k = k0 + kt;
            float4 xv = *(const float4*)&Xs[k * XS_ROW + 4 * l];
            const ulonglong2* bp = (const ulonglong2*)&Tile[kt * NSMALL + 8 * w];
            ulonglong2 b0 = bp[0], b1 = bp[1], b2 = bp[2], b3 = bp[3];
            u64v bb[8] = {b0.x, b0.y, b1.x, b1.y, b2.x, b2.y, b3.x, b3.y};
            float xsv[4] = {xv.x, xv.y, xv.z, xv.w};
            #pragma unroll
            for (int pp = 0; pp < 4; pp++) {
                u64v xs2 = pk2(xsv[pp], xsv[pp]);
                #pragma unroll
                for (int jj = 0; jj < 8; jj++) ffma2(acc[pp][jj], xs2, bb[jj]);
            }
        }
    }

    // --- write T into smem (reusing Xs region): Ts[p][j], row pitch 66 ---
    __syncthreads();
    float2* Ts = (float2*)smem;
    #pragma unroll
    for (int pp = 0; pp < 4; pp++)
        #pragma unroll
        for (int jp = 0; jp < 4; jp++)
            *(ulonglong2*)&Ts[(4 * l + pp) * TS_ROW + 8 * w + 2 * jp] =
                make_ulonglong2(acc[pp][2 * jp], acc[pp][2 * jp + 1]);

    // ---- GEMM2: thread computes O[{l,l+32}][8w..8w+7] ----
    // accA = sum a.re*(t.re,t.im), accB = sum a.im*(t.re,t.im)
    u64v accA[2][8], accB[2][8];
    #pragma unroll
    for (int ii = 0; ii < 2; ii++)
        #pragma unroll
        for (int jj = 0; jj < 8; jj++) { accA[ii][jj] = 0ull; accB[ii][jj] = 0ull; }

    for (int p0 = 0; p0 < NBIG; p0 += KCHUNK) {
        __syncthreads();
        {
            const ulonglong2* g = (const ulonglong2*)(d_At + (size_t)p0 * NSMALL);
            ulonglong2* t = (ulonglong2*)Tile;
            #pragma unroll
            for (int i = 0; i < (KCHUNK * NSMALL) / (2 * 256); i++)
                t[tid + i * 256] = g[tid + i * 256];
        }
        __syncthreads();
        #pragma unroll
        for (int pt = 0; pt < KCHUNK; pt++) {
            int p = p0 + pt;
            float2 a0 = Tile[pt * NSMALL + l];
            float2 a1 = Tile[pt * NSMALL + l + 32];
            const ulonglong2* tp = (const ulonglong2*)&Ts[p * TS_ROW + 8 * w];
            ulonglong2 t0 = tp[0], t1 = tp[1], t2 = tp[2], t3 = tp[3];
            u64v tt[8] = {t0.x, t0.y, t1.x, t1.y, t2.x, t2.y, t3.x, t3.y};
            u64v ax0 = pk2(a0.x, a0.x), ay0 = pk2(a0.y, a0.y);
            u64v ax1 = pk2(a1.x, a1.x), ay1 = pk2(a1.y, a1.y);
            #pragma unroll
            for (int jj = 0; jj < 8; jj++) {
                ffma2(accA[0][jj], ax0, tt[jj]);
                ffma2(accB[0][jj], ay0, tt[jj]);
                ffma2(accA[1][jj], ax1, tt[jj]);
                ffma2(accB[1][jj], ay1, tt[jj]);
            }
        }
    }

    float* og = out + (size_t)img * (NSMALL * NSMALL);
    #pragma unroll
    for (int ii = 0; ii < 2; ii++) {
        int i = l + 32 * ii;
        float res[8];
        #pragma unroll
        for (int jj = 0; jj < 8; jj++) {
            float Ar, Ai, Br, Bi;
            upk2(Ar, Ai, accA[ii][jj]);
            upk2(Br, Bi, accB[ii][jj]);
            float orr = Ar - Bi;
            float oii = Ai + Br;
            res[jj] = sqrtf(orr * orr + oii * oii);
        }
        *(float4*)&og[i * NSMALL + 8 * w]     = make_float4(res[0], res[1], res[2], res[3]);
        *(float4*)&og[i * NSMALL + 8 * w + 4] = make_float4(res[4], res[5], res[6], res[7]);
    }
}

// ---------------------------------------------------------------------
extern "C" void kernel_launch(void* const* d_in, const int* in_sizes, int n_in,
                              void* d_out, int out_size) {
    const float* x  = (const float*)d_in[0];
    const float* o1 = (const float*)d_in[1];
    const float* o2 = (const float*)d_in[2];
    float* out = (float*)d_out;

    build_tables<<<4, 512>>>(o1, o2);
    build_matrix<<<dim3(NBIG, 4), 128>>>();
    combine<<<dim3(NSMALL, 2), 128>>>();

    cudaFuncSetAttribute(frft_pool_main,
                         cudaFuncAttributeMaxDynamicSharedMemorySize, SMEM_BYTES);
    frft_pool_main<<<NIMG, 256, SMEM_BYTES>>>(x, out);
}

// round 6
// speedup vs baseline: 1.4164x; 1.1690x over previous
#include <cuda_runtime.h>
#include <math.h>

// =====================================================================
// FrFTPool: out = |A · X · B^T| per 128x128 image; A,B (64x128 complex)
// built on-device from the Candan/Ozaktas FrFT closed form with the
// center crop folded in. GEMMs use packed fma.rn.f32x2 (FFMA2).
// =====================================================================

#define NBIG 128
#define NSMALL 64
#define NIMG 256          // 8*32
#define XS_ROW 132        // padded row for transposed X in smem (floats)
#define TS_ROW 66         // padded row for T in smem (float2)
#define KCHUNK 32         // k/p tile depth for Tile staging

typedef unsigned long long u64v;

__device__ __forceinline__ u64v pk2(float lo, float hi) {
    u64v r; asm("mov.b64 %0, {%1, %2};" : "=l"(r) : "f"(lo), "f"(hi)); return r;
}
__device__ __forceinline__ void upk2(float& lo, float& hi, u64v v) {
    asm("mov.b64 {%0, %1}, %2;" : "=f"(lo), "=f"(hi) : "l"(v));
}
__device__ __forceinline__ void ffma2(u64v& d, u64v a, u64v b) {
    asm("fma.rn.f32x2 %0, %1, %2, %0;" : "+l"(d) : "l"(a), "l"(b));
}

// ---------------- device scratch (no allocations allowed) -------------
__device__ __align__(16) float2 d_M1[NBIG * NBIG];
__device__ __align__(16) float2 d_M2[NBIG * NBIG];
__device__ __align__(16) float2 d_M3[NSMALL * NSMALL];
__device__ __align__(16) float2 d_M4[NSMALL * NSMALL];
__device__ __align__(16) float2 d_At[NBIG * NSMALL];   // At[h][i] = A[i][h]
__device__ __align__(16) float2 d_Bt[NBIG * NSMALL];   // Bt[k][j] = B[j][k]

__device__ __align__(16) float2 d_Ktab[4][4 * NBIG];   // up to 4N-3 = 509
__device__ __align__(16) float2 d_Ctab[4][2 * NBIG];   // up to 2N-1 = 255
__device__ float2 d_pref[4];
__device__ int    d_flip[4];

// ---------------- 1) chirp tables (DP sincos, sliced across 32 blocks) -
// matrix m = blockIdx.x: 0 -> order1 @N=128, 1 -> order2 @N=128,
//                        2 -> -order1 @N=64,  3 -> -order2 @N=64
// slice  s = blockIdx.y in [0,8): each block fills 1/8 of the tables.
__global__ void build_tables(const float* __restrict__ order1,
                             const float* __restrict__ order2) {
    int m = blockIdx.x;
    int s = blockIdx.y;
    int N = (m < 2) ? NBIG : NSMALL;
    float ap = ((m == 0) || (m == 2)) ? order1[0] : order2[0];
    if (m >= 2) ap = -ap;

    double a = fmod((double)ap, 4.0);
    if (a < 0.0) a += 4.0;
    int flip = 0;
    if (a > 2.0) { flip = 1; a -= 2.0; }

    double alpha = a * M_PI * 0.5;
    double tana2 = tan(alpha * 0.5);
    double sina  = sin(alpha);
    double c     = M_PI / (4.0 * (double)N * sina);
    double kch   = (M_PI / (double)N) * tana2 * 0.25;

    int t = threadIdx.x;                 // 0..127
    int nK = 4 * N - 3;
    int nC = 2 * N - 1;
    // K slice: global index i = s*128 + t (grid-stride not needed: 8*128 >= 509)
    int i = s * 128 + t;
    if (i < nK) {
        double mm = (double)(i - (2 * N - 2));
        double sn, co; sincos(c * mm * mm, &sn, &co);
        d_Ktab[m][i] = make_float2((float)co, (float)sn);
    }
    // C slice: 8 blocks x 32 threads covers 256 >= 255
    if (t < 32) {
        int p = s * 32 + t;
        if (p < nC) {
            double n = (double)(p - (N - 1));
            double sn, co; sincos(-kch * n * n, &sn, &co);
            d_Ctab[m][p] = make_float2((float)co, (float)sn);
        }
    }
    if (s == 0 && t == 0) {
        double ph = -(1.0 - a) * M_PI * 0.25;
        double sn, co; sincos(ph, &sn, &co);
        double sc = sqrt(c / M_PI);
        d_pref[m] = make_float2((float)(co * sc), (float)(sn * sc));
        d_flip[m] = flip;
    }
}

// ---------------- 2) FrFT matrices from tables (fp32 only) ------------
// M[j,k] = pref*C[2j]*( K[2(j-kk)]*C[2kk] + sum_t KC[t]*W[|t-kk|] )
//   kk = flip ? N-1-k : k,  KC[t] = K[2j-2t-1]*C[2t+1],
//   W[i] = ((i&1)?-2:2)/(pi*(2i+1))
__global__ void build_matrix() {
    int m = blockIdx.y;
    int N = (m < 2) ? NBIG : NSMALL;
    int j = blockIdx.x;
    if (j >= N) return;

    __shared__ float2 Ks[4 * NBIG];
    __shared__ float2 Cs[2 * NBIG];
    __shared__ float  W[NBIG];
    __shared__ float2 KC[NBIG];

    int tid = threadIdx.x;
    for (int i = tid; i < 4 * N - 3; i += 128) Ks[i] = d_Ktab[m][i];
    for (int p = tid; p < 2 * N - 1; p += 128) Cs[p] = d_Ctab[m][p];
    if (tid < N)
        W[tid] = ((tid & 1) ? -2.0f : 2.0f) / ((float)M_PI * (float)(2 * tid + 1));
    __syncthreads();

    int off = 2 * N - 2;
    if (tid < N - 1) {
        float2 K = Ks[2 * j - 2 * tid - 1 + off];
        float2 C = Cs[2 * tid + 1];
        KC[tid] = make_float2(K.x * C.x - K.y * C.y, K.x * C.y + K.y * C.x);
    }
    __syncthreads();

    int k = tid;
    if (k >= N) return;
    int flip = d_flip[m];
    int kk = flip ? (N - 1 - k) : k;

    float2 Ke = Ks[2 * (j - kk) + off];
    float2 Ce = Cs[2 * kk];
    float sr = Ke.x * Ce.x - Ke.y * Ce.y;
    float si = Ke.x * Ce.y + Ke.y * Ce.x;

    #pragma unroll 4
    for (int t = 0; t < N - 1; t++) {
        int u = t - kk;
        int idx = u ^ (u >> 31);
        float sv = W[idx];
        float2 kc = KC[t];
        sr = fmaf(kc.x, sv, sr);
        si = fmaf(kc.y, sv, si);
    }

    float2 pr = d_pref[m];
    float2 Cj = Cs[2 * j];
    float pcr = pr.x * Cj.x - pr.y * Cj.y;
    float pci = pr.x * Cj.y + pr.y * Cj.x;
    float2 outv;
    outv.x = pcr * sr - pci * si;
    outv.y = pcr * si + pci * sr;

    float2* M = (m == 0) ? d_M1 : (m == 1) ? d_M2 : (m == 2) ? d_M3 : d_M4;
    M[j * N + k] = outv;
}

// ---------------- 3) fold crop into combined matrices -----------------
// A[i,h] = sum_p M4[i,p] * M2[32+p, h]   -> stored transposed At[h][i]
// B[j,k] = sum_q M3[j,q] * M1[32+q, k]   -> stored transposed Bt[k][j]
__global__ void combine() {
    int i = blockIdx.x;          // 0..63 output row of A/B
    int h = threadIdx.x;         // 0..127 input column
    const float2* L = blockIdx.y ? d_M3 : d_M4;   // 64x64
    const float2* R = blockIdx.y ? d_M1 : d_M2;   // 128x128
    float ar = 0.f, ai = 0.f;
    #pragma unroll 4
    for (int p = 0; p < NSMALL; p++) {
        float2 l = L[i * NSMALL + p];
        float2 r = R[(32 + p) * NBIG + h];
        ar += l.x * r.x - l.y * r.y;
        ai += l.x * r.y + l.y * r.x;
    }
    float2* T = blockIdx.y ? d_Bt : d_At;
    T[h * NSMALL + i] = make_float2(ar, ai);
}

// ---------------- 4) main fused kernel: per-image |A·X·B^T| -----------
// block = 256 threads, one image per block.
// GEMM1: T[p,j] = sum_k X[p,k]*B[j,k]   (X real)   p<128, j<64
// GEMM2: O[i,j] = | sum_p A[i,p]*T[p,j] |          i<64,  j<64
#define SMEM_BYTES (NBIG * XS_ROW * 4 + KCHUNK * NSMALL * 8)  // 67584 + 16384

__global__ __launch_bounds__(256, 2)
void frft_pool_main(const float* __restrict__ x, float* __restrict__ out) {
    extern __shared__ float smem[];
    float*  Xs   = smem;                                // [128][132] floats
    float2* Tile = (float2*)(smem + NBIG * XS_ROW);     // [KCHUNK][64] float2

    int tid = threadIdx.x;
    int l = tid & 31;        // lane
    int w = tid >> 5;        // warp 0..7
    int img = blockIdx.x;

    // --- load X transposed into smem: Xs[k][p] = X[p][k] ---
    const float4* xg4 = (const float4*)(x + (size_t)img * (NBIG * NBIG));
    #pragma unroll
    for (int i = 0; i < 16; i++) {
        int idx4 = tid + i * 256;
        float4 v = xg4[idx4];
        int r = idx4 >> 5;            // row p
        int c = (idx4 & 31) << 2;     // col k base
        Xs[(c + 0) * XS_ROW + r] = v.x;
        Xs[(c + 1) * XS_ROW + r] = v.y;
        Xs[(c + 2) * XS_ROW + r] = v.z;
        Xs[(c + 3) * XS_ROW + r] = v.w;
    }

    // ---- GEMM1: thread computes T[4l..4l+3][8w..8w+7], packed (re,im) ----
    u64v acc[4][8];
    #pragma unroll
    for (int pp = 0; pp < 4; pp++)
        #pragma unroll
        for (int jj = 0; jj < 8; jj++) acc[pp][jj] = 0ull;

    for (int k0 = 0; k0 < NBIG; k0 += KCHUNK) {
        __syncthreads();
        {
            const ulonglong2* g = (const ulonglong2*)(d_Bt + (size_t)k0 * NSMALL);
            ulonglong2* t = (ulonglong2*)Tile;
            #pragma unroll
            for (int i = 0; i < (KCHUNK * NSMALL) / (2 * 256); i++)
                t[tid + i * 256] = g[tid + i * 256];
        }
        __syncthreads();
        #pragma unroll
        for (int kt = 0; kt < KCHUNK; kt++) {
            int k = k0 + kt;
            float4 xv = *(const float4*)&Xs[k * XS_ROW + 4 * l];
            const ulonglong2* bp = (const ulonglong2*)&Tile[kt * NSMALL + 8 * w];
            ulonglong2 b0 = bp[0], b1 = bp[1], b2 = bp[2], b3 = bp[3];
            u64v bb[8] = {b0.x, b0.y, b1.x, b1.y, b2.x, b2.y, b3.x, b3.y};
            float xsv[4] = {xv.x, xv.y, xv.z, xv.w};
            #pragma unroll
            for (int pp = 0; pp < 4; pp++) {
                u64v xs2 = pk2(xsv[pp], xsv[pp]);
                #pragma unroll
                for (int jj = 0; jj < 8; jj++) ffma2(acc[pp][jj], xs2, bb[jj]);
            }
        }
    }

    // --- write T into smem (reusing Xs region): Ts[p][j], row pitch 66 ---
    __syncthreads();
    float2* Ts = (float2*)smem;
    #pragma unroll
    for (int pp = 0; pp < 4; pp++)
        #pragma unroll
        for (int jp = 0; jp < 4; jp++)
            *(ulonglong2*)&Ts[(4 * l + pp) * TS_ROW + 8 * w + 2 * jp] =
                make_ulonglong2(acc[pp][2 * jp], acc[pp][2 * jp + 1]);

    // ---- GEMM2: thread computes O[{l,l+32}][8w..8w+7] ----
    // accA = sum a.re*(t.re,t.im), accB = sum a.im*(t.re,t.im)
    u64v accA[2][8], accB[2][8];
    #pragma unroll
    for (int ii = 0; ii < 2; ii++)
        #pragma unroll
        for (int jj = 0; jj < 8; jj++) { accA[ii][jj] = 0ull; accB[ii][jj] = 0ull; }

    for (int p0 = 0; p0 < NBIG; p0 += KCHUNK) {
        __syncthreads();
        {
            const ulonglong2* g = (const ulonglong2*)(d_At + (size_t)p0 * NSMALL);
            ulonglong2* t = (ulonglong2*)Tile;
            #pragma unroll
            for (int i = 0; i < (KCHUNK * NSMALL) / (2 * 256); i++)
                t[tid + i * 256] = g[tid + i * 256];
        }
        __syncthreads();
        #pragma unroll
        for (int pt = 0; pt < KCHUNK; pt++) {
            int p = p0 + pt;
            float2 a0 = Tile[pt * NSMALL + l];
            float2 a1 = Tile[pt * NSMALL + l + 32];
            const ulonglong2* tp = (const ulonglong2*)&Ts[p * TS_ROW + 8 * w];
            ulonglong2 t0 = tp[0], t1 = tp[1], t2 = tp[2], t3 = tp[3];
            u64v tt[8] = {t0.x, t0.y, t1.x, t1.y, t2.x, t2.y, t3.x, t3.y};
            u64v ax0 = pk2(a0.x, a0.x), ay0 = pk2(a0.y, a0.y);
            u64v ax1 = pk2(a1.x, a1.x), ay1 = pk2(a1.y, a1.y);
            #pragma unroll
            for (int jj = 0; jj < 8; jj++) {
                ffma2(accA[0][jj], ax0, tt[jj]);
                ffma2(accB[0][jj], ay0, tt[jj]);
                ffma2(accA[1][jj], ax1, tt[jj]);
                ffma2(accB[1][jj], ay1, tt[jj]);
            }
        }
    }

    float* og = out + (size_t)img * (NSMALL * NSMALL);
    #pragma unroll
    for (int ii = 0; ii < 2; ii++) {
        int i = l + 32 * ii;
        float res[8];
        #pragma unroll
        for (int jj = 0; jj < 8; jj++) {
            float Ar, Ai, Br, Bi;
            upk2(Ar, Ai, accA[ii][jj]);
            upk2(Br, Bi, accB[ii][jj]);
            float orr = Ar - Bi;
            float oii = Ai + Br;
            res[jj] = sqrtf(orr * orr + oii * oii);
        }
        *(float4*)&og[i * NSMALL + 8 * w]     = make_float4(res[0], res[1], res[2], res[3]);
        *(float4*)&og[i * NSMALL + 8 * w + 4] = make_float4(res[4], res[5], res[6], res[7]);
    }
}

// ---------------------------------------------------------------------
extern "C" void kernel_launch(void* const* d_in, const int* in_sizes, int n_in,
                              void* d_out, int out_size) {
    const float* x  = (const float*)d_in[0];
    const float* o1 = (const float*)d_in[1];
    const float* o2 = (const float*)d_in[2];
    float* out = (float*)d_out;

    build_tables<<<dim3(4, 8), 128>>>(o1, o2);
    build_matrix<<<dim3(NBIG, 4), 128>>>();
    combine<<<dim3(NSMALL, 2), 128>>>();

    cudaFuncSetAttribute(frft_pool_main,
                         cudaFuncAttributeMaxDynamicSharedMemorySize, SMEM_BYTES);
    frft_pool_main<<<NIMG, 256, SMEM_BYTES>>>(x, out);
}